// round 5
// baseline (speedup 1.0000x reference)
#include <cuda_runtime.h>
#include <math.h>

#define Bn 16
#define C  128
#define P  4096      // 64*64
#define TD 256
#define CD 256
#define E  8
#define NK 2

// ---------------- scratch ---------------------------------------------------
__device__ float g_xproj[Bn*C*P];       // x_proj
__device__ float g_pooled[Bn*C];        // SUM over pixels (mean applied in router)
__device__ int   g_eidx[Bn*NK];
__device__ float g_ew[Bn*NK];

__device__ __forceinline__ float silu_f(float v) {
    return v / (1.f + __expf(-v));
}

__device__ __forceinline__ float tf32r(float x) {
    unsigned u;
    asm("cvt.rna.tf32.f32 %0, %1;" : "=r"(u) : "f"(x));
    return __uint_as_float(u);
}

__device__ __forceinline__ void mma_tf32(float* c,
                                         unsigned a0, unsigned a1, unsigned a2, unsigned a3,
                                         unsigned b0, unsigned b1) {
    asm volatile("mma.sync.aligned.m16n8k8.row.col.f32.tf32.tf32.f32 "
                 "{%0,%1,%2,%3}, {%4,%5,%6,%7}, {%8,%9}, {%0,%1,%2,%3};"
                 : "+f"(c[0]), "+f"(c[1]), "+f"(c[2]), "+f"(c[3])
                 : "r"(a0), "r"(a1), "r"(a2), "r"(a3), "r"(b0), "r"(b1));
}

// 3x3 depthwise on one 4-px quad of row y, input plane xp (64x64)
__device__ __forceinline__ void dw_quad(const float* __restrict__ xp, int y, int px0,
                                        const float* __restrict__ wc, float bb,
                                        float& a0, float& a1, float& a2, float& a3) {
    a0 = bb; a1 = bb; a2 = bb; a3 = bb;
    #pragma unroll
    for (int dy = -1; dy <= 1; dy++) {
        int yy = y + dy;
        if ((unsigned)yy >= 64u) continue;
        const float* row = xp + (yy << 6);
        float4 m = *(const float4*)&row[px0];
        float rl = (px0 == 0)  ? 0.f : row[px0 - 1];
        float rr = (px0 == 60) ? 0.f : row[px0 + 4];
        float w0 = wc[(dy+1)*3], w1 = wc[(dy+1)*3+1], w2 = wc[(dy+1)*3+2];
        a0 += w0*rl  + w1*m.x + w2*m.y;
        a1 += w0*m.x + w1*m.y + w2*m.z;
        a2 += w0*m.y + w1*m.z + w2*m.w;
        a3 += w0*m.z + w1*m.w + w2*rr;
    }
}

// ---------------- 0) zero pooled accumulator --------------------------------
__global__ void zero_pooled_kernel() {
    int t = blockIdx.x * blockDim.x + threadIdx.x;
    if (t < Bn * C) g_pooled[t] = 0.f;
}

// ---------------- 1) fused proj: dw3x3 -> pw GEMM (tf32 MMA) -> pool -------
// grid (64 rows, 16 b), 256 thr. Block tile 128co x 64px (one image row).
#define WS_P 36     // Wsm row stride (conflict-free A-frag: bank=4g+t4)
#define BS_S 72     // Bsm row stride (conflict-free B-frag: bank=8*t4+g)
__global__ __launch_bounds__(256)
void fused_proj_kernel(const float* __restrict__ x,
                       const float* __restrict__ dw_w, const float* __restrict__ dw_b,
                       const float* __restrict__ Wm,   const float* __restrict__ bias) {
    int y  = blockIdx.x;                  // image row = 64-px GEMM tile
    int b  = blockIdx.y;
    int tx = threadIdx.x;
    int wid = tx >> 5, lane = tx & 31;
    int wm = wid >> 1, wn = wid & 1;
    int g = lane >> 2, t4 = lane & 3;
    __shared__ float Wsm[128 * WS_P];
    __shared__ float Bsm[32 * BS_S];
    float acc[2][4][4];
    #pragma unroll
    for (int i = 0; i < 2; i++)
        #pragma unroll
        for (int j = 0; j < 4; j++)
            #pragma unroll
            for (int l = 0; l < 4; l++) acc[i][j][l] = 0.f;

    for (int c0 = 0; c0 < C; c0 += 32) {
        __syncthreads();
        #pragma unroll
        for (int i = 0; i < 4; i++) {            // W chunk 128x32
            int slot = i * 256 + tx;
            int co = slot >> 3, k4 = slot & 7;
            float4 v = *(const float4*)&Wm[co * C + c0 + k4 * 4];
            float* d = &Wsm[co * WS_P + k4 * 4];
            d[0] = tf32r(v.x); d[1] = tf32r(v.y); d[2] = tf32r(v.z); d[3] = tf32r(v.w);
        }
        #pragma unroll
        for (int q = 0; q < 2; q++) {            // dw: 32ch x 64px = 512 quads
            int quad = q * 256 + tx;
            int k = quad >> 4;
            int px0 = (quad & 15) << 2;
            int c = c0 + k;
            const float* xp = x + ((size_t)(b * C + c) << 12);
            float a0, a1, a2, a3;
            dw_quad(xp, y, px0, dw_w + c * 9, dw_b[c], a0, a1, a2, a3);
            float* d = &Bsm[k * BS_S + px0];
            d[0] = tf32r(a0); d[1] = tf32r(a1); d[2] = tf32r(a2); d[3] = tf32r(a3);
        }
        __syncthreads();
        #pragma unroll
        for (int kk = 0; kk < 4; kk++) {
            int kb = kk * 8;
            unsigned af[2][4];
            #pragma unroll
            for (int mt = 0; mt < 2; mt++) {
                int r0 = wm * 32 + mt * 16 + g;
                af[mt][0] = __float_as_uint(Wsm[r0 * WS_P + kb + t4]);
                af[mt][1] = __float_as_uint(Wsm[(r0 + 8) * WS_P + kb + t4]);
                af[mt][2] = __float_as_uint(Wsm[r0 * WS_P + kb + t4 + 4]);
                af[mt][3] = __float_as_uint(Wsm[(r0 + 8) * WS_P + kb + t4 + 4]);
            }
            #pragma unroll
            for (int nt = 0; nt < 4; nt++) {
                int col = wn * 32 + nt * 8 + g;
                unsigned b0 = __float_as_uint(Bsm[(kb + t4) * BS_S + col]);
                unsigned b1 = __float_as_uint(Bsm[(kb + t4 + 4) * BS_S + col]);
                #pragma unroll
                for (int mt = 0; mt < 2; mt++)
                    mma_tf32(acc[mt][nt], af[mt][0], af[mt][1], af[mt][2], af[mt][3], b0, b1);
            }
        }
    }
    // epilogue: bias, store xproj row, pooled partial sums
    #pragma unroll
    for (int mt = 0; mt < 2; mt++) {
        int r0 = wm * 32 + mt * 16 + g;
        float bb0 = bias[r0], bb8 = bias[r0 + 8];
        float s0 = 0.f, s8 = 0.f;
        #pragma unroll
        for (int nt = 0; nt < 4; nt++) {
            int col = (y << 6) + wn * 32 + nt * 8 + 2 * t4;
            float* o0 = g_xproj + ((((size_t)b * C) + r0) << 12) + col;
            float* o8 = g_xproj + ((((size_t)b * C) + r0 + 8) << 12) + col;
            float v0 = acc[mt][nt][0] + bb0, v1 = acc[mt][nt][1] + bb0;
            float v2 = acc[mt][nt][2] + bb8, v3 = acc[mt][nt][3] + bb8;
            *(float2*)o0 = make_float2(v0, v1);
            *(float2*)o8 = make_float2(v2, v3);
            s0 += v0 + v1; s8 += v2 + v3;
        }
        s0 += __shfl_down_sync(0xffffffffu, s0, 2, 4);
        s0 += __shfl_down_sync(0xffffffffu, s0, 1, 4);
        s8 += __shfl_down_sync(0xffffffffu, s8, 2, 4);
        s8 += __shfl_down_sync(0xffffffffu, s8, 1, 4);
        if (t4 == 0) {
            atomicAdd(&g_pooled[b * C + r0], s0);
            atomicAdd(&g_pooled[b * C + r0 + 8], s8);
        }
    }
}

// ---------------- 2) router: per-b block, fused MLP+top2 -------------------
__global__ __launch_bounds__(1024)
void router_kernel(const float* __restrict__ t_emb,
                   const float* __restrict__ c_emb,
                   const float* __restrict__ W1, const float* __restrict__ b1,
                   const float* __restrict__ W2, const float* __restrict__ b2,
                   float* __restrict__ out_logits) {
    int b = blockIdx.x;
    __shared__ float feat[C + TD + CD];
    __shared__ float hpart[8][C];
    __shared__ float h[C];
    __shared__ float lgp[8][E];
    __shared__ float lg[E];
    int t = threadIdx.x;
    if (t < C + TD + CD) {
        float v;
        if (t < C)            v = g_pooled[b * C + t] * (1.f / 4096.f);
        else if (t < C + TD)  v = t_emb[b * TD + (t - C)];
        else                  v = c_emb[b * CD + (t - C - TD)];
        feat[t] = v;
    }
    __syncthreads();
    int co = t & 127, chunk = t >> 7;           // 8 chunks of 80 features
    {
        float a0 = 0.f, a1 = 0.f, a2 = 0.f, a3 = 0.f;
        int f0 = chunk * 80;
        #pragma unroll
        for (int f = f0; f < f0 + 80; f += 4) {
            a0 += feat[f]     * W1[f * C + co];
            a1 += feat[f + 1] * W1[(f + 1) * C + co];
            a2 += feat[f + 2] * W1[(f + 2) * C + co];
            a3 += feat[f + 3] * W1[(f + 3) * C + co];
        }
        hpart[chunk][co] = (a0 + a1) + (a2 + a3);
    }
    __syncthreads();
    if (t < C) {
        float v = b1[t];
        #pragma unroll
        for (int i = 0; i < 8; i++) v += hpart[i][t];
        h[t] = silu_f(v);
    }
    __syncthreads();
    if (t < 64) {
        int e = t & 7, pp = t >> 3;
        float a = 0.f;
        int c0 = pp * 16;
        #pragma unroll
        for (int ci = c0; ci < c0 + 16; ci++) a += h[ci] * W2[ci * E + e];
        lgp[pp][e] = a;
    }
    __syncthreads();
    if (t < E) {
        float a = b2[t];
        #pragma unroll
        for (int i = 0; i < 8; i++) a += lgp[i][t];
        lg[t] = a;
        out_logits[b * E + t] = a;
    }
    __syncthreads();
    if (t == 0) {
        int i0 = 0; float v0 = lg[0];
        for (int e = 1; e < E; e++) if (lg[e] > v0) { v0 = lg[e]; i0 = e; }
        int i1 = -1; float v1 = -3.0e38f;
        for (int e = 0; e < E; e++) {
            if (e == i0) continue;
            if (lg[e] > v1) { v1 = lg[e]; i1 = e; }
        }
        float w0 = 1.f / (1.f + __expf(v1 - v0));
        g_eidx[b*2]   = i0;  g_eidx[b*2+1] = i1;
        g_ew[b*2]     = w0;  g_ew[b*2+1]   = 1.f - w0;
    }
}

// ---------------- 3) fused experts: dw3x3 x2 -> pw GEMM x2 -> silu+mix -----
#define WS_E 20     // Wsm row stride KC=16 (conflict-free: bank=(20g+t4)%32)
__global__ __launch_bounds__(256)
void fused_exp_kernel(const float* __restrict__ dw_w, const float* __restrict__ dw_b,
                      const float* __restrict__ Wm,   const float* __restrict__ bias,
                      float* __restrict__ out) {
    int y  = blockIdx.x;
    int b  = blockIdx.y;
    int tx = threadIdx.x;
    int wid = tx >> 5, lane = tx & 31;
    int wm = wid >> 1, wn = wid & 1;
    int g = lane >> 2, t4 = lane & 3;
    int e0 = g_eidx[b*2], e1 = g_eidx[b*2+1];
    float rw0 = g_ew[b*2], rw1 = g_ew[b*2+1];
    __shared__ float Wsm0[128 * WS_E], Wsm1[128 * WS_E];
    __shared__ float Bsm0[16 * BS_S],  Bsm1[16 * BS_S];
    float a0c[2][4][4], a1c[2][4][4];
    #pragma unroll
    for (int i = 0; i < 2; i++)
        #pragma unroll
        for (int j = 0; j < 4; j++)
            #pragma unroll
            for (int l = 0; l < 4; l++) { a0c[i][j][l] = 0.f; a1c[i][j][l] = 0.f; }

    const float* W0 = Wm + (size_t)e0 * C * C;
    const float* W1 = Wm + (size_t)e1 * C * C;
    for (int c0 = 0; c0 < C; c0 += 16) {
        __syncthreads();
        #pragma unroll
        for (int i = 0; i < 2; i++) {            // W chunks 128x16 each expert
            int slot = i * 256 + tx;
            int co = slot >> 2, k4 = slot & 3;
            float4 v0 = *(const float4*)&W0[co * C + c0 + k4 * 4];
            float4 v1 = *(const float4*)&W1[co * C + c0 + k4 * 4];
            float* d0 = &Wsm0[co * WS_E + k4 * 4];
            float* d1 = &Wsm1[co * WS_E + k4 * 4];
            d0[0]=tf32r(v0.x); d0[1]=tf32r(v0.y); d0[2]=tf32r(v0.z); d0[3]=tf32r(v0.w);
            d1[0]=tf32r(v1.x); d1[1]=tf32r(v1.y); d1[2]=tf32r(v1.z); d1[3]=tf32r(v1.w);
        }
        {                                        // dw both experts: 16ch x 64px = 256 quads
            int k = tx >> 4;
            int px0 = (tx & 15) << 2;
            int c = c0 + k;
            const float* xp = g_xproj + ((size_t)(b * C + c) << 12);
            const float* wcA = dw_w + ((size_t)e0 * C + c) * 9;
            const float* wcB = dw_w + ((size_t)e1 * C + c) * 9;
            float bA = dw_b[e0 * C + c], bB = dw_b[e1 * C + c];
            float A0 = bA, A1 = bA, A2 = bA, A3 = bA;
            float B0 = bB, B1 = bB, B2 = bB, B3 = bB;
            #pragma unroll
            for (int dy = -1; dy <= 1; dy++) {
                int yy = y + dy;
                if ((unsigned)yy >= 64u) continue;
                const float* row = xp + (yy << 6);
                float4 m = *(const float4*)&row[px0];
                float rl = (px0 == 0)  ? 0.f : row[px0 - 1];
                float rr = (px0 == 60) ? 0.f : row[px0 + 4];
                float wa0 = wcA[(dy+1)*3], wa1 = wcA[(dy+1)*3+1], wa2 = wcA[(dy+1)*3+2];
                float wb0 = wcB[(dy+1)*3], wb1 = wcB[(dy+1)*3+1], wb2 = wcB[(dy+1)*3+2];
                A0 += wa0*rl  + wa1*m.x + wa2*m.y;
                A1 += wa0*m.x + wa1*m.y + wa2*m.z;
                A2 += wa0*m.y + wa1*m.z + wa2*m.w;
                A3 += wa0*m.z + wa1*m.w + wa2*rr;
                B0 += wb0*rl  + wb1*m.x + wb2*m.y;
                B1 += wb0*m.x + wb1*m.y + wb2*m.z;
                B2 += wb0*m.y + wb1*m.z + wb2*m.w;
                B3 += wb0*m.z + wb1*m.w + wb2*rr;
            }
            float* d0 = &Bsm0[k * BS_S + px0];
            float* d1 = &Bsm1[k * BS_S + px0];
            d0[0]=tf32r(A0); d0[1]=tf32r(A1); d0[2]=tf32r(A2); d0[3]=tf32r(A3);
            d1[0]=tf32r(B0); d1[1]=tf32r(B1); d1[2]=tf32r(B2); d1[3]=tf32r(B3);
        }
        __syncthreads();
        #pragma unroll
        for (int kk = 0; kk < 2; kk++) {
            int kb = kk * 8;
            unsigned af0[2][4], af1[2][4];
            #pragma unroll
            for (int mt = 0; mt < 2; mt++) {
                int r0 = wm * 32 + mt * 16 + g;
                af0[mt][0] = __float_as_uint(Wsm0[r0 * WS_E + kb + t4]);
                af0[mt][1] = __float_as_uint(Wsm0[(r0 + 8) * WS_E + kb + t4]);
                af0[mt][2] = __float_as_uint(Wsm0[r0 * WS_E + kb + t4 + 4]);
                af0[mt][3] = __float_as_uint(Wsm0[(r0 + 8) * WS_E + kb + t4 + 4]);
                af1[mt][0] = __float_as_uint(Wsm1[r0 * WS_E + kb + t4]);
                af1[mt][1] = __float_as_uint(Wsm1[(r0 + 8) * WS_E + kb + t4]);
                af1[mt][2] = __float_as_uint(Wsm1[r0 * WS_E + kb + t4 + 4]);
                af1[mt][3] = __float_as_uint(Wsm1[(r0 + 8) * WS_E + kb + t4 + 4]);
            }
            #pragma unroll
            for (int nt = 0; nt < 4; nt++) {
                int col = wn * 32 + nt * 8 + g;
                unsigned b00 = __float_as_uint(Bsm0[(kb + t4) * BS_S + col]);
                unsigned b01 = __float_as_uint(Bsm0[(kb + t4 + 4) * BS_S + col]);
                unsigned b10 = __float_as_uint(Bsm1[(kb + t4) * BS_S + col]);
                unsigned b11 = __float_as_uint(Bsm1[(kb + t4 + 4) * BS_S + col]);
                #pragma unroll
                for (int mt = 0; mt < 2; mt++) {
                    mma_tf32(a0c[mt][nt], af0[mt][0], af0[mt][1], af0[mt][2], af0[mt][3], b00, b01);
                    mma_tf32(a1c[mt][nt], af1[mt][0], af1[mt][1], af1[mt][2], af1[mt][3], b10, b11);
                }
            }
        }
    }
    #pragma unroll
    for (int mt = 0; mt < 2; mt++) {
        int r0 = wm * 32 + mt * 16 + g;
        float b00 = bias[e0 * C + r0], b08 = bias[e0 * C + r0 + 8];
        float b10 = bias[e1 * C + r0], b18 = bias[e1 * C + r0 + 8];
        #pragma unroll
        for (int nt = 0; nt < 4; nt++) {
            int col = (y << 6) + wn * 32 + nt * 8 + 2 * t4;
            float* o0 = out + ((((size_t)b * C) + r0) << 12) + col;
            float* o8 = out + ((((size_t)b * C) + r0 + 8) << 12) + col;
            float v0 = rw0 * silu_f(a0c[mt][nt][0] + b00) + rw1 * silu_f(a1c[mt][nt][0] + b10);
            float v1 = rw0 * silu_f(a0c[mt][nt][1] + b00) + rw1 * silu_f(a1c[mt][nt][1] + b10);
            float v2 = rw0 * silu_f(a0c[mt][nt][2] + b08) + rw1 * silu_f(a1c[mt][nt][2] + b18);
            float v3 = rw0 * silu_f(a0c[mt][nt][3] + b08) + rw1 * silu_f(a1c[mt][nt][3] + b18);
            *(float2*)o0 = make_float2(v0, v1);
            *(float2*)o8 = make_float2(v2, v3);
        }
    }
}

// ---------------- launch ----------------------------------------------------
extern "C" void kernel_launch(void* const* d_in, const int* in_sizes, int n_in,
                              void* d_out, int out_size) {
    const float* x         = (const float*)d_in[0];
    const float* t_emb     = (const float*)d_in[1];
    const float* c_emb     = (const float*)d_in[2];
    const float* proj_dw   = (const float*)d_in[3];
    const float* proj_dw_b = (const float*)d_in[4];
    const float* proj_pw   = (const float*)d_in[5];
    const float* proj_pw_b = (const float*)d_in[6];
    const float* r_w1      = (const float*)d_in[7];
    const float* r_b1      = (const float*)d_in[8];
    const float* r_w2      = (const float*)d_in[9];
    const float* r_b2      = (const float*)d_in[10];
    const float* exp_dw    = (const float*)d_in[11];
    const float* exp_dw_b  = (const float*)d_in[12];
    const float* exp_pw    = (const float*)d_in[13];
    const float* exp_pw_b  = (const float*)d_in[14];

    float* out        = (float*)d_out;
    float* out_logits = out + (size_t)Bn * C * P;

    zero_pooled_kernel<<<(Bn*C + 255) / 256, 256>>>();
    fused_proj_kernel<<<dim3(64, Bn), 256>>>(x, proj_dw, proj_dw_b, proj_pw, proj_pw_b);
    router_kernel<<<Bn, 1024>>>(t_emb, c_emb, r_w1, r_b1, r_w2, r_b2, out_logits);
    fused_exp_kernel<<<dim3(64, Bn), 256>>>(exp_dw, exp_dw_b, exp_pw, exp_pw_b, out);
}